// round 1
// baseline (speedup 1.0000x reference)
#include <cuda_runtime.h>
#include <math.h>

#define B_    8
#define T_    2048
#define DIN   512
#define DA    8
#define DOUT  512

// Scratch (static __device__ globals: allocation-free, allowed)
__device__ __align__(16) float g_Q[B_ * T_ * DA];
__device__ __align__(16) float g_K[B_ * T_ * DA];
__device__ __align__(16) float g_V[B_ * T_ * DOUT];

// ---------------------------------------------------------------------------
// Kernel 1: Q,K projections. One warp per token; 8 tokens per 256-thread CTA.
// Q[t,f] = sum_d X[t,d] * Wq[d,f]   (f = 0..7), likewise K.
// ---------------------------------------------------------------------------
__global__ __launch_bounds__(256) void qk_kernel(const float* __restrict__ X,
                                                 const float* __restrict__ Wq,
                                                 const float* __restrict__ Wk) {
    int warp = threadIdx.x >> 5;
    int lane = threadIdx.x & 31;
    int tok  = blockIdx.x * 8 + warp;           // grid = B_*T_/8
    const float* x = X + (size_t)tok * DIN;

    float aq[8], ak[8];
#pragma unroll
    for (int f = 0; f < 8; f++) { aq[f] = 0.f; ak[f] = 0.f; }

#pragma unroll 4
    for (int d = lane; d < DIN; d += 32) {
        float xv = x[d];
        float4 q0 = *(const float4*)(Wq + (size_t)d * 8);
        float4 q1 = *(const float4*)(Wq + (size_t)d * 8 + 4);
        float4 k0 = *(const float4*)(Wk + (size_t)d * 8);
        float4 k1 = *(const float4*)(Wk + (size_t)d * 8 + 4);
        aq[0] += xv * q0.x; aq[1] += xv * q0.y; aq[2] += xv * q0.z; aq[3] += xv * q0.w;
        aq[4] += xv * q1.x; aq[5] += xv * q1.y; aq[6] += xv * q1.z; aq[7] += xv * q1.w;
        ak[0] += xv * k0.x; ak[1] += xv * k0.y; ak[2] += xv * k0.z; ak[3] += xv * k0.w;
        ak[4] += xv * k1.x; ak[5] += xv * k1.y; ak[6] += xv * k1.z; ak[7] += xv * k1.w;
    }

#pragma unroll
    for (int f = 0; f < 8; f++) {
        aq[f] += __shfl_xor_sync(0xffffffffu, aq[f], 16);
        aq[f] += __shfl_xor_sync(0xffffffffu, aq[f], 8);
        aq[f] += __shfl_xor_sync(0xffffffffu, aq[f], 4);
        aq[f] += __shfl_xor_sync(0xffffffffu, aq[f], 2);
        aq[f] += __shfl_xor_sync(0xffffffffu, aq[f], 1);
        ak[f] += __shfl_xor_sync(0xffffffffu, ak[f], 16);
        ak[f] += __shfl_xor_sync(0xffffffffu, ak[f], 8);
        ak[f] += __shfl_xor_sync(0xffffffffu, ak[f], 4);
        ak[f] += __shfl_xor_sync(0xffffffffu, ak[f], 2);
        ak[f] += __shfl_xor_sync(0xffffffffu, ak[f], 1);
    }

    if (lane < 8) {
        // tiny local-array dynamic index is fine here
        g_Q[(size_t)tok * 8 + lane] = aq[lane];
    } else if (lane < 16) {
        g_K[(size_t)tok * 8 + (lane - 8)] = ak[lane - 8];
    }
}

// ---------------------------------------------------------------------------
// Kernel 2: V = X @ Wv.  Classic fp32 SGEMM, BM=BN=128, BK=16, 256 threads,
// 8x8 register micro-tiles with 64-strided halves (conflict-free LDS.128).
// M = B_*T_ = 16384, N = K = 512.
// ---------------------------------------------------------------------------
__global__ __launch_bounds__(256) void vproj_kernel(const float* __restrict__ A,
                                                    const float* __restrict__ Bw) {
    __shared__ float As[16][132];   // transposed A tile, padded rows
    __shared__ float Bs[16][128];

    int t  = threadIdx.x;
    int bm = blockIdx.y;            // 0..127
    int bn = blockIdx.x;            // 0..3
    int tr = t >> 4;                // 0..15
    int tc = t & 15;                // 0..15

    const float* Ag = A + (size_t)bm * 128 * DIN;
    const float* Bg = Bw + (size_t)bn * 128;

    float acc[8][8];
#pragma unroll
    for (int i = 0; i < 8; i++)
#pragma unroll
        for (int j = 0; j < 8; j++) acc[i][j] = 0.f;

    for (int kt = 0; kt < DIN; kt += 16) {
        // Load A tile 128x16 (512 float4s), store transposed
#pragma unroll
        for (int e = t; e < 512; e += 256) {
            int row = e >> 2;
            int cg  = (e & 3) << 2;
            float4 v = *(const float4*)(Ag + (size_t)row * DIN + kt + cg);
            As[cg + 0][row] = v.x;
            As[cg + 1][row] = v.y;
            As[cg + 2][row] = v.z;
            As[cg + 3][row] = v.w;
        }
        // Load B tile 16x128 (512 float4s)
#pragma unroll
        for (int e = t; e < 512; e += 256) {
            int row = e >> 5;              // 0..15
            int cg  = (e & 31) << 2;       // 0..124
            *(float4*)(&Bs[row][cg]) =
                *(const float4*)(Bg + (size_t)(kt + row) * DOUT + cg);
        }
        __syncthreads();

#pragma unroll
        for (int k = 0; k < 16; k++) {
            float a0[8], b0[8];
            *(float4*)(a0)     = *(const float4*)(&As[k][tr * 4]);
            *(float4*)(a0 + 4) = *(const float4*)(&As[k][tr * 4 + 64]);
            *(float4*)(b0)     = *(const float4*)(&Bs[k][tc * 4]);
            *(float4*)(b0 + 4) = *(const float4*)(&Bs[k][tc * 4 + 64]);
#pragma unroll
            for (int i = 0; i < 8; i++)
#pragma unroll
                for (int j = 0; j < 8; j++)
                    acc[i][j] += a0[i] * b0[j];
        }
        __syncthreads();
    }

#pragma unroll
    for (int i = 0; i < 8; i++) {
        int rr = tr * 4 + ((i & 4) ? 64 : 0) + (i & 3);
        float* cp = g_V + (size_t)(bm * 128 + rr) * DOUT + bn * 128;
        *(float4*)(cp + tc * 4)      = make_float4(acc[i][0], acc[i][1], acc[i][2], acc[i][3]);
        *(float4*)(cp + tc * 4 + 64) = make_float4(acc[i][4], acc[i][5], acc[i][6], acc[i][7]);
    }
}

// ---------------------------------------------------------------------------
// Kernel 3: sparse-softmax attention. One warp per query row.
// Pass 1: s8[i] = (q . k_s)^8 for all 2048 keys, track row max m.
// Pass 2: p = exp(s8 - m); psum accumulates ALL p (exact denominator);
//         only lanes with p > 1e-10 trigger a warp-cooperative V-row gather.
// Correct regardless of sparsity; fast because softmax(x^8) is near one-hot.
// ---------------------------------------------------------------------------
__global__ __launch_bounds__(256) void attn_kernel(float* __restrict__ Out) {
    int warp = threadIdx.x >> 5;
    int lane = threadIdx.x & 31;
    int q    = blockIdx.x * 8 + warp;          // 0..16383
    int b    = q >> 11;                        // q / 2048
    const float* Kb = g_K + (size_t)b * T_ * DA;
    const float* Vb = g_V + (size_t)b * T_ * DOUT;

    float4 qa = *(const float4*)(g_Q + (size_t)q * DA);
    float4 qb = *(const float4*)(g_Q + (size_t)q * DA + 4);

    float s8v[64];                             // 2048 keys / 32 lanes
    float m = -INFINITY;

#pragma unroll 1
    for (int i = 0; i < 64; i++) {
        int s = i * 32 + lane;                 // coalesced K rows
        const float4* kp = (const float4*)(Kb + (size_t)s * DA);
        float4 k0 = kp[0];
        float4 k1 = kp[1];
        float d = qa.x * k0.x + qa.y * k0.y + qa.z * k0.z + qa.w * k0.w
                + qb.x * k1.x + qb.y * k1.y + qb.z * k1.z + qb.w * k1.w;
        float d2 = d * d;
        float d4 = d2 * d2;
        float d8 = d4 * d4;
        s8v[i] = d8;
        m = fmaxf(m, d8);
    }
    m = fmaxf(m, __shfl_xor_sync(0xffffffffu, m, 16));
    m = fmaxf(m, __shfl_xor_sync(0xffffffffu, m, 8));
    m = fmaxf(m, __shfl_xor_sync(0xffffffffu, m, 4));
    m = fmaxf(m, __shfl_xor_sync(0xffffffffu, m, 2));
    m = fmaxf(m, __shfl_xor_sync(0xffffffffu, m, 1));

    float acc0 = 0.f, acc1 = 0.f, acc2 = 0.f, acc3 = 0.f;
    float acc4 = 0.f, acc5 = 0.f, acc6 = 0.f, acc7 = 0.f;
    float acc8 = 0.f, acc9 = 0.f, accA = 0.f, accB = 0.f;
    float accC = 0.f, accD = 0.f, accE = 0.f, accF = 0.f;
    float psum = 0.f;

#pragma unroll 1
    for (int i = 0; i < 64; i++) {
        float p = __expf(s8v[i] - m);
        psum += p;
        unsigned ball = __ballot_sync(0xffffffffu, p > 1e-10f);
        while (ball) {
            int src = __ffs(ball) - 1;
            ball &= ball - 1;
            float pv = __shfl_sync(0xffffffffu, p, src);
            int s = i * 32 + src;
            const float4* vp = (const float4*)(Vb + (size_t)s * DOUT) + lane * 4;
            float4 v0 = vp[0];
            float4 v1 = vp[1];
            float4 v2 = vp[2];
            float4 v3 = vp[3];
            acc0 += pv * v0.x; acc1 += pv * v0.y; acc2 += pv * v0.z; acc3 += pv * v0.w;
            acc4 += pv * v1.x; acc5 += pv * v1.y; acc6 += pv * v1.z; acc7 += pv * v1.w;
            acc8 += pv * v2.x; acc9 += pv * v2.y; accA += pv * v2.z; accB += pv * v2.w;
            accC += pv * v3.x; accD += pv * v3.y; accE += pv * v3.z; accF += pv * v3.w;
        }
    }

    psum += __shfl_xor_sync(0xffffffffu, psum, 16);
    psum += __shfl_xor_sync(0xffffffffu, psum, 8);
    psum += __shfl_xor_sync(0xffffffffu, psum, 4);
    psum += __shfl_xor_sync(0xffffffffu, psum, 2);
    psum += __shfl_xor_sync(0xffffffffu, psum, 1);
    float inv = 1.f / psum;

    float4* op = (float4*)(Out + (size_t)q * DOUT) + lane * 4;
    op[0] = make_float4(acc0 * inv, acc1 * inv, acc2 * inv, acc3 * inv);
    op[1] = make_float4(acc4 * inv, acc5 * inv, acc6 * inv, acc7 * inv);
    op[2] = make_float4(acc8 * inv, acc9 * inv, accA * inv, accB * inv);
    op[3] = make_float4(accC * inv, accD * inv, accE * inv, accF * inv);
}

// ---------------------------------------------------------------------------
extern "C" void kernel_launch(void* const* d_in, const int* in_sizes, int n_in,
                              void* d_out, int out_size) {
    (void)in_sizes; (void)n_in; (void)out_size;
    const float* X  = (const float*)d_in[0];
    const float* Wq = (const float*)d_in[1];
    const float* Wk = (const float*)d_in[2];
    const float* Wv = (const float*)d_in[3];
    // d_in[4] = power, constant 8 for this problem (hardcoded in attn_kernel)
    float* Out = (float*)d_out;

    qk_kernel<<<(B_ * T_) / 8, 256>>>(X, Wq, Wk);
    vproj_kernel<<<dim3(DOUT / 128, (B_ * T_) / 128), 256>>>(X, Wv);
    attn_kernel<<<(B_ * T_) / 8, 256>>>(Out);
}